// round 9
// baseline (speedup 1.0000x reference)
#include <cuda_runtime.h>
#include <cuda_fp16.h>

// Problem constants
#define B   2
#define D   160
#define H   192
#define W   160
#define HW  (H * W)          // 30720
#define DHW (D * H * W)      // 4915200
#define NVOX (B * DHW)       // 9830400 per channel
#define CH  5
#define WIN 9
#define PAD 4
#define INV_N (1.0f / 729.0f)

// 4-half units (pass3)
#define W4    (W / 4)        // 40
#define HW4   (HW / 4)       // 7680
#define DHW4  (DHW / 4)      // 1228800
#define NVOX4 (NVOX / 4)     // 2457600

// float4 units (grad)
#define WQ   (W / 4)         // 40
#define HWQ  (HW / 4)        // 7680
#define DHWQ (DHW / 4)       // 1228800

// H segmentation for k_pass12
#define HSEG  64
#define NSEGH (H / HSEG)     // 3

// D segmentation for k_pass3
#define SEG3  4
#define DSEG3 (D / SEG3)     // 40

// D segmentation for k_grad
#define GSEGD 4
#define GDSEG (D / GSEGD)    // 40

// Scratch — fp16 box-sums, uint2-typed for 8B alignment
__device__ uint2 g_bufH4[CH * NVOX4];
__device__ double g_acc[4];           // cc_sum, dx_sum, dy_sum, dz_sum

__device__ __forceinline__ void warp_reduce_atomic(float v, double* dst) {
#pragma unroll
    for (int off = 16; off > 0; off >>= 1)
        v += __shfl_down_sync(0xFFFFFFFFu, v, off);
    if ((threadIdx.x & 31) == 0) atomicAdd(dst, (double)v);
}

__device__ __forceinline__ float4 h4_to_f4(uint2 u) {
    const __half2 a = *reinterpret_cast<const __half2*>(&u.x);
    const __half2 b = *reinterpret_cast<const __half2*>(&u.y);
    const float2 fa = __half22float2(a);
    const float2 fb = __half22float2(b);
    return make_float4(fa.x, fa.y, fb.x, fb.y);
}

__global__ void k_zero() {
    if (threadIdx.x < 4) g_acc[threadIdx.x] = 0.0;
}

// ---------------------------------------------------------------------------
// Fused pass 1+2, chunked: 4 rows staged per barrier; fp16 output stores.
__global__ void k_pass12(const float* __restrict__ F, const float* __restrict__ M) {
    __shared__ float stg[2][4][2][W + 2 * PAD];  // [buf][row][f/m][w]
    __shared__ float ring[WIN][CH][W];

    __half* __restrict__ bufH = (__half*)g_bufH4;

    const int w = threadIdx.x;
    int blk = blockIdx.x;                        // over B*D*NSEGH = 960
    const int hs = blk % NSEGH; blk /= NSEGH;
    const int d  = blk % D;
    const int b  = blk / D;
    const int h0 = hs * HSEG;

    const size_t plane = (size_t)(b * D + d) * HW;
    const float* __restrict__ Fp = F + plane;
    const float* __restrict__ Mp = M + plane;

#pragma unroll
    for (int sl = 0; sl < WIN; sl++)
#pragma unroll
        for (int c = 0; c < CH; c++) ring[sl][c][w] = 0.f;

    if (w < PAD) {
#pragma unroll
        for (int bu = 0; bu < 2; bu++)
#pragma unroll
            for (int r = 0; r < 4; r++)
#pragma unroll
                for (int c = 0; c < 2; c++) {
                    stg[bu][r][c][w] = 0.f;
                    stg[bu][r][c][w + W + PAD] = 0.f;
                }
    }
    __syncthreads();

    float s0 = 0.f, s1 = 0.f, s2 = 0.f, s3 = 0.f, s4 = 0.f;

#define STAGE(bu, r0, nr)                                                    \
    {                                                                        \
        _Pragma("unroll")                                                    \
        for (int i = 0; i < (nr); i++) {                                     \
            const int r_ = (r0) + i;                                         \
            const bool valid_ = (r_ >= 0 && r_ < H);                         \
            stg[bu][i][0][w + PAD] = valid_ ? Fp[r_ * W + w] : 0.f;          \
            stg[bu][i][1][w + PAD] = valid_ ? Mp[r_ * W + w] : 0.f;          \
        }                                                                    \
        __syncthreads();                                                     \
    }

#define PROC(bu, i, r)                                                       \
    {                                                                        \
        float n0 = 0.f, n1 = 0.f, n2 = 0.f, n3 = 0.f, n4 = 0.f;              \
        _Pragma("unroll")                                                    \
        for (int k = 0; k < WIN; k++) {                                      \
            const float fk = stg[bu][i][0][w + k];                           \
            const float mk = stg[bu][i][1][w + k];                           \
            n0 += fk; n1 += mk;                                              \
            n2 = fmaf(fk, fk, n2);                                           \
            n3 = fmaf(mk, mk, n3);                                           \
            n4 = fmaf(fk, mk, n4);                                           \
        }                                                                    \
        const int slot = ((r) + 18) % 9;                                     \
        s0 += n0 - ring[slot][0][w]; ring[slot][0][w] = n0;                  \
        s1 += n1 - ring[slot][1][w]; ring[slot][1][w] = n1;                  \
        s2 += n2 - ring[slot][2][w]; ring[slot][2][w] = n2;                  \
        s3 += n3 - ring[slot][3][w]; ring[slot][3][w] = n3;                  \
        s4 += n4 - ring[slot][4][w]; ring[slot][4][w] = n4;                  \
    }

#define EMIT(h_)                                                             \
    {                                                                        \
        const size_t o = plane + (size_t)(h_) * W + w;                       \
        bufH[0 * NVOX + o] = __float2half_rn(s0);                            \
        bufH[1 * NVOX + o] = __float2half_rn(s1);                            \
        bufH[2 * NVOX + o] = __float2half_rn(s2);                            \
        bufH[3 * NVOX + o] = __float2half_rn(s3);                            \
        bufH[4 * NVOX + o] = __float2half_rn(s4);                            \
    }

    STAGE(0, h0 - 4, 4);
    PROC(0, 0, h0 - 4) PROC(0, 1, h0 - 3) PROC(0, 2, h0 - 2) PROC(0, 3, h0 - 1)
    STAGE(1, h0, 4);
    PROC(1, 0, h0) PROC(1, 1, h0 + 1) PROC(1, 2, h0 + 2) PROC(1, 3, h0 + 3)
    STAGE(0, h0 + 4, 1);
    PROC(0, 0, h0 + 4)

#pragma unroll 1
    for (int ci = 0; ci < HSEG / 4; ci++) {
        const int h = h0 + ci * 4;
        if (ci & 1) {
            STAGE(0, h + 5, 4);
            EMIT(h);
            PROC(0, 0, h + 5) EMIT(h + 1);
            PROC(0, 1, h + 6) EMIT(h + 2);
            PROC(0, 2, h + 7) EMIT(h + 3);
            PROC(0, 3, h + 8)
        } else {
            STAGE(1, h + 5, 4);
            EMIT(h);
            PROC(1, 0, h + 5) EMIT(h + 1);
            PROC(1, 1, h + 6) EMIT(h + 2);
            PROC(1, 2, h + 7) EMIT(h + 3);
            PROC(1, 3, h + 8)
        }
    }
#undef STAGE
#undef PROC
#undef EMIT
}

// ---------------------------------------------------------------------------
// Pass 3: register D-ring over fp16 planes. Thread owns 4 halves (uint2);
// fp32 running sums; each bufH element loaded exactly once per segment.
__global__ void __launch_bounds__(160) k_pass3_cc() {
    const int t = threadIdx.x;
    const int qw = t % W4;                   // uint2 index in row (0..39)
    const int hs = t / W4;                   // 0..3
    int blk = blockIdx.x;                    // over B * (H/4) * SEG3 = 384
    const int seg = blk % SEG3; blk /= SEG3;
    const int hq = blk % (H / 4);
    const int b  = blk / (H / 4);
    const int h  = hq * 4 + hs;
    const int d0 = seg * DSEG3;

    const size_t col = (size_t)b * DHW4 + (size_t)h * W4 + qw;

    uint2 ring[WIN][CH];
    float4 s[CH];
#pragma unroll
    for (int c = 0; c < CH; c++) s[c] = make_float4(0.f, 0.f, 0.f, 0.f);

    // Prologue: planes d0-4 .. d0+4 (d0+4 <= 124 < D always)
#pragma unroll
    for (int i = 0; i < WIN; i++) {
        const int d = d0 - PAD + i;
        const bool v = (d >= 0);
#pragma unroll
        for (int c = 0; c < CH; c++) {
            uint2 x = make_uint2(0u, 0u);
            if (v) x = __ldcs(&g_bufH4[(size_t)c * NVOX4 + col + (size_t)d * HW4]);
            ring[i][c] = x;
            const float4 f = h4_to_f4(x);
            s[c].x += f.x; s[c].y += f.y; s[c].z += f.z; s[c].w += f.w;
        }
    }

    float local = 0.f;
#pragma unroll
    for (int u = 0; u < DSEG3; u++) {
#define CCC(comp)                                                            \
        {                                                                    \
            const float mf  = s[0].comp * INV_N;                             \
            const float mm  = s[1].comp * INV_N;                             \
            const float vF  = s[2].comp - mf * mf;                           \
            const float vM  = s[3].comp - mm * mm;                           \
            const float cov = s[4].comp - mf * mm;                           \
            local += (cov * cov) / (vF * vM + 1e-8f);                        \
        }
        CCC(x) CCC(y) CCC(z) CCC(w)
#undef CCC

        const int dn = d0 + u + PAD + 1;     // incoming plane
        const int slot = u % 9;              // literal under full unroll
        if (dn < D) {
#pragma unroll
            for (int c = 0; c < CH; c++) {
                const uint2 nv = __ldcs(&g_bufH4[(size_t)c * NVOX4 + col + (size_t)dn * HW4]);
                const float4 fa = h4_to_f4(nv);
                const float4 fo = h4_to_f4(ring[slot][c]);
                s[c].x += fa.x - fo.x; s[c].y += fa.y - fo.y;
                s[c].z += fa.z - fo.z; s[c].w += fa.w - fo.w;
                ring[slot][c] = nv;
            }
        } else {
#pragma unroll
            for (int c = 0; c < CH; c++) {
                const float4 fo = h4_to_f4(ring[slot][c]);
                s[c].x -= fo.x; s[c].y -= fo.y; s[c].z -= fo.z; s[c].w -= fo.w;
                ring[slot][c] = make_uint2(0u, 0u);
            }
        }
    }

    warp_reduce_atomic(local, &g_acc[0]);
}

// ---------------------------------------------------------------------------
// Flow gradient: d-walk with register reuse (unchanged, runs on side stream).
__global__ void k_grad(const float* __restrict__ flow) {
    const float4* __restrict__ f4 = (const float4*)flow;
    const int t = threadIdx.x;
    const int qw = t % WQ;
    const int hs = t / WQ;                   // 0..3
    int blk = blockIdx.x;                    // over B*3 * (H/4) * GSEGD = 1152
    const int seg = blk % GSEGD; blk /= GSEGD;
    const int hq = blk % (H / 4);
    const int bc = blk / (H / 4);            // 0..5 (b*3 + c)
    const int h  = hq * 4 + hs;
    const int d0 = seg * GDSEG;

    const bool hasH = (h < H - 1);
    const bool hasW = (qw < WQ - 1);

    size_t base = (size_t)bc * DHWQ + (size_t)d0 * HWQ + (size_t)h * WQ + qw;
    float sdx = 0.f, sdy = 0.f, sdz = 0.f;
    float4 v = f4[base];

    const int dend = d0 + GDSEG;
#pragma unroll 4
    for (int d = d0; d < dend; d++) {
        sdz += fabsf(v.y - v.x) + fabsf(v.z - v.y) + fabsf(v.w - v.z);
        if (hasW) sdz += fabsf(flow[4 * base + 4] - v.w);
        if (hasH) {
            const float4 hn = f4[base + WQ];
            sdx += fabsf(hn.x - v.x) + fabsf(hn.y - v.y)
                 + fabsf(hn.z - v.z) + fabsf(hn.w - v.w);
        }
        if (d < D - 1) {
            const float4 dn = f4[base + HWQ];
            sdy += fabsf(dn.x - v.x) + fabsf(dn.y - v.y)
                 + fabsf(dn.z - v.z) + fabsf(dn.w - v.w);
            v = dn;
        }
        base += HWQ;
    }

    warp_reduce_atomic(sdx, &g_acc[1]);
    warp_reduce_atomic(sdy, &g_acc[2]);
    warp_reduce_atomic(sdz, &g_acc[3]);
}

// ---------------------------------------------------------------------------
__global__ void k_finalize(float* __restrict__ out) {
    const double L_sim = -(g_acc[0] / (double)NVOX);
    const double ndx = (double)B * 3.0 * D * (H - 1) * W;
    const double ndy = (double)B * 3.0 * (D - 1) * H * W;
    const double ndz = (double)B * 3.0 * D * H * (W - 1);
    const double L_reg = g_acc[1] / ndx + g_acc[2] / ndy + g_acc[3] / ndz;
    out[0] = (float)(L_sim + L_reg);
    out[1] = (float)L_sim;
    out[2] = (float)L_reg;
}

// ---------------------------------------------------------------------------
extern "C" void kernel_launch(void* const* d_in, const int* in_sizes, int n_in,
                              void* d_out, int out_size) {
    const float* I_fixed = (const float*)d_in[0];
    const float* I_moved = (const float*)d_in[1];
    const float* flow    = (const float*)d_in[2];
    float* out = (float*)d_out;

    static cudaStream_t s_side = 0;
    static cudaEvent_t ev_fork = 0, ev_join = 0;
    if (s_side == 0) {
        cudaStreamCreateWithFlags(&s_side, cudaStreamNonBlocking);
        cudaEventCreateWithFlags(&ev_fork, cudaEventDisableTiming);
        cudaEventCreateWithFlags(&ev_join, cudaEventDisableTiming);
    }

    k_zero<<<1, 32>>>();

    // Fork: k_grad (reads flow only) runs concurrently with pass12/pass3.
    cudaEventRecord(ev_fork, 0);
    cudaStreamWaitEvent(s_side, ev_fork, 0);
    k_grad<<<B * 3 * (H / 4) * GSEGD, 160, 0, s_side>>>(flow);
    cudaEventRecord(ev_join, s_side);

    k_pass12<<<B * D * NSEGH, W>>>(I_fixed, I_moved);
    k_pass3_cc<<<B * (H / 4) * SEG3, 160>>>();

    cudaStreamWaitEvent(0, ev_join, 0);
    k_finalize<<<1, 1>>>(out);
}

// round 10
// speedup vs baseline: 1.1819x; 1.1819x over previous
#include <cuda_runtime.h>
#include <cuda_fp16.h>

// Problem constants
#define B   2
#define D   160
#define H   192
#define W   160
#define HW  (H * W)          // 30720
#define DHW (D * H * W)      // 4915200
#define NVOX (B * DHW)       // 9830400 per channel
#define CH  5
#define WIN 9
#define PAD 4
#define INV_N (1.0f / 729.0f)

// 4-half units (pass3)
#define W4    (W / 4)        // 40
#define HW4   (HW / 4)       // 7680
#define DHW4  (DHW / 4)      // 1228800
#define NVOX4 (NVOX / 4)     // 2457600

// float4 units (grad)
#define WQ   (W / 4)         // 40
#define HWQ  (HW / 4)        // 7680
#define DHWQ (DHW / 4)       // 1228800

// H segmentation for k_pass12
#define HSEG  64
#define NSEGH (H / HSEG)     // 3

// D segmentation for k_pass3
#define SEG3  8
#define DSEG3 (D / SEG3)     // 20

// D segmentation for k_grad
#define GSEGD 4
#define GDSEG (D / GSEGD)    // 40

// Scratch — fp16 box-sums, uint2-typed for 8B alignment
__device__ uint2 g_bufH4[CH * NVOX4];
__device__ double g_acc[4];           // cc_sum, dx_sum, dy_sum, dz_sum

__device__ __forceinline__ void warp_reduce_atomic(float v, double* dst) {
#pragma unroll
    for (int off = 16; off > 0; off >>= 1)
        v += __shfl_down_sync(0xFFFFFFFFu, v, off);
    if ((threadIdx.x & 31) == 0) atomicAdd(dst, (double)v);
}

__device__ __forceinline__ float4 h4_to_f4(uint2 u) {
    const __half2 a = *reinterpret_cast<const __half2*>(&u.x);
    const __half2 b = *reinterpret_cast<const __half2*>(&u.y);
    const float2 fa = __half22float2(a);
    const float2 fb = __half22float2(b);
    return make_float4(fa.x, fa.y, fb.x, fb.y);
}

__global__ void k_zero() {
    if (threadIdx.x < 4) g_acc[threadIdx.x] = 0.0;
}

// ---------------------------------------------------------------------------
// Fused pass 1+2, chunked staging; fp16 output with shuffle-packed half2 stores.
__global__ void k_pass12(const float* __restrict__ F, const float* __restrict__ M) {
    __shared__ float stg[2][4][2][W + 2 * PAD];  // [buf][row][f/m][w]
    __shared__ float ring[WIN][CH][W];

    __half2* __restrict__ bufH2 = (__half2*)g_bufH4;

    const int w = threadIdx.x;
    int blk = blockIdx.x;                        // over B*D*NSEGH = 960
    const int hs = blk % NSEGH; blk /= NSEGH;
    const int d  = blk % D;
    const int b  = blk / D;
    const int h0 = hs * HSEG;

    const size_t plane = (size_t)(b * D + d) * HW;
    const float* __restrict__ Fp = F + plane;
    const float* __restrict__ Mp = M + plane;
    const bool even = ((w & 1) == 0);

#pragma unroll
    for (int sl = 0; sl < WIN; sl++)
#pragma unroll
        for (int c = 0; c < CH; c++) ring[sl][c][w] = 0.f;

    if (w < PAD) {
#pragma unroll
        for (int bu = 0; bu < 2; bu++)
#pragma unroll
            for (int r = 0; r < 4; r++)
#pragma unroll
                for (int c = 0; c < 2; c++) {
                    stg[bu][r][c][w] = 0.f;
                    stg[bu][r][c][w + W + PAD] = 0.f;
                }
    }
    __syncthreads();

    float s0 = 0.f, s1 = 0.f, s2 = 0.f, s3 = 0.f, s4 = 0.f;

#define STAGE(bu, r0, nr)                                                    \
    {                                                                        \
        _Pragma("unroll")                                                    \
        for (int i = 0; i < (nr); i++) {                                     \
            const int r_ = (r0) + i;                                         \
            const bool valid_ = (r_ >= 0 && r_ < H);                         \
            stg[bu][i][0][w + PAD] = valid_ ? Fp[r_ * W + w] : 0.f;          \
            stg[bu][i][1][w + PAD] = valid_ ? Mp[r_ * W + w] : 0.f;          \
        }                                                                    \
        __syncthreads();                                                     \
    }

#define PROC(bu, i, r)                                                       \
    {                                                                        \
        float n0 = 0.f, n1 = 0.f, n2 = 0.f, n3 = 0.f, n4 = 0.f;              \
        _Pragma("unroll")                                                    \
        for (int k = 0; k < WIN; k++) {                                      \
            const float fk = stg[bu][i][0][w + k];                           \
            const float mk = stg[bu][i][1][w + k];                           \
            n0 += fk; n1 += mk;                                              \
            n2 = fmaf(fk, fk, n2);                                           \
            n3 = fmaf(mk, mk, n3);                                           \
            n4 = fmaf(fk, mk, n4);                                           \
        }                                                                    \
        const int slot = ((r) + 18) % 9;                                     \
        s0 += n0 - ring[slot][0][w]; ring[slot][0][w] = n0;                  \
        s1 += n1 - ring[slot][1][w]; ring[slot][1][w] = n1;                  \
        s2 += n2 - ring[slot][2][w]; ring[slot][2][w] = n2;                  \
        s3 += n3 - ring[slot][3][w]; ring[slot][3][w] = n3;                  \
        s4 += n4 - ring[slot][4][w]; ring[slot][4][w] = n4;                  \
    }

    // Even lanes store packed {own, lane+1} half2 per channel.
#define EMIT(h_)                                                             \
    {                                                                        \
        const float t0 = __shfl_down_sync(0xFFFFFFFFu, s0, 1);               \
        const float t1 = __shfl_down_sync(0xFFFFFFFFu, s1, 1);               \
        const float t2 = __shfl_down_sync(0xFFFFFFFFu, s2, 1);               \
        const float t3 = __shfl_down_sync(0xFFFFFFFFu, s3, 1);               \
        const float t4 = __shfl_down_sync(0xFFFFFFFFu, s4, 1);               \
        if (even) {                                                          \
            const size_t o2 = (plane + (size_t)(h_) * W + w) >> 1;           \
            bufH2[((size_t)0 * NVOX >> 1) + o2] = __floats2half2_rn(s0, t0); \
            bufH2[((size_t)1 * NVOX >> 1) + o2] = __floats2half2_rn(s1, t1); \
            bufH2[((size_t)2 * NVOX >> 1) + o2] = __floats2half2_rn(s2, t2); \
            bufH2[((size_t)3 * NVOX >> 1) + o2] = __floats2half2_rn(s3, t3); \
            bufH2[((size_t)4 * NVOX >> 1) + o2] = __floats2half2_rn(s4, t4); \
        }                                                                    \
    }

    STAGE(0, h0 - 4, 4);
    PROC(0, 0, h0 - 4) PROC(0, 1, h0 - 3) PROC(0, 2, h0 - 2) PROC(0, 3, h0 - 1)
    STAGE(1, h0, 4);
    PROC(1, 0, h0) PROC(1, 1, h0 + 1) PROC(1, 2, h0 + 2) PROC(1, 3, h0 + 3)
    STAGE(0, h0 + 4, 1);
    PROC(0, 0, h0 + 4)

#pragma unroll 1
    for (int ci = 0; ci < HSEG / 4; ci++) {
        const int h = h0 + ci * 4;
        if (ci & 1) {
            STAGE(0, h + 5, 4);
            EMIT(h);
            PROC(0, 0, h + 5) EMIT(h + 1);
            PROC(0, 1, h + 6) EMIT(h + 2);
            PROC(0, 2, h + 7) EMIT(h + 3);
            PROC(0, 3, h + 8)
        } else {
            STAGE(1, h + 5, 4);
            EMIT(h);
            PROC(1, 0, h + 5) EMIT(h + 1);
            PROC(1, 1, h + 6) EMIT(h + 2);
            PROC(1, 2, h + 7) EMIT(h + 3);
            PROC(1, 3, h + 8)
        }
    }
#undef STAGE
#undef PROC
#undef EMIT
}

// ---------------------------------------------------------------------------
// Pass 3: two-pointer D running window (NO ring). Add-stream loads plane d+5,
// sub-stream re-loads plane d-4 (L2-served: re-read distance ~5.5MB « L2).
// Thread owns 4 halves (uint2 loads), fp32 accumulators. ~60 regs.
__global__ void __launch_bounds__(160) k_pass3_cc() {
    const int t = threadIdx.x;
    const int qw = t % W4;                   // uint2 index in row (0..39)
    const int hs = t / W4;                   // 0..3
    int blk = blockIdx.x;                    // over B * (H/4) * SEG3 = 768
    const int seg = blk % SEG3; blk /= SEG3;
    const int hq = blk % (H / 4);
    const int b  = blk / (H / 4);
    const int h  = hq * 4 + hs;
    const int d0 = seg * DSEG3;

    const size_t col = (size_t)b * DHW4 + (size_t)h * W4 + qw;

    float4 s[CH];
#pragma unroll
    for (int c = 0; c < CH; c++) s[c] = make_float4(0.f, 0.f, 0.f, 0.f);

    // Prologue: sum planes d0-4 .. d0+4 (upper bound d0+4 <= 144 < D)
#pragma unroll 1
    for (int i = 0; i < WIN; i++) {
        const int d = d0 - PAD + i;
        if (d >= 0) {
#pragma unroll
            for (int c = 0; c < CH; c++) {
                const float4 f = h4_to_f4(g_bufH4[(size_t)c * NVOX4 + col + (size_t)d * HW4]);
                s[c].x += f.x; s[c].y += f.y; s[c].z += f.z; s[c].w += f.w;
            }
        }
    }

    float local = 0.f;
#pragma unroll 2
    for (int u = 0; u < DSEG3; u++) {
        const int d = d0 + u;
#define CCC(comp)                                                            \
        {                                                                    \
            const float mf  = s[0].comp * INV_N;                             \
            const float mm  = s[1].comp * INV_N;                             \
            const float vF  = s[2].comp - mf * mf;                           \
            const float vM  = s[3].comp - mm * mm;                           \
            const float cov = s[4].comp - mf * mm;                           \
            local += (cov * cov) / (vF * vM + 1e-8f);                        \
        }
        CCC(x) CCC(y) CCC(z) CCC(w)
#undef CCC

        const int dn = d + PAD + 1;
        const int dm = d - PAD;
        if (dn < D) {
#pragma unroll
            for (int c = 0; c < CH; c++) {
                const float4 f = h4_to_f4(g_bufH4[(size_t)c * NVOX4 + col + (size_t)dn * HW4]);
                s[c].x += f.x; s[c].y += f.y; s[c].z += f.z; s[c].w += f.w;
            }
        }
        if (dm >= 0) {
#pragma unroll
            for (int c = 0; c < CH; c++) {
                const float4 f = h4_to_f4(g_bufH4[(size_t)c * NVOX4 + col + (size_t)dm * HW4]);
                s[c].x -= f.x; s[c].y -= f.y; s[c].z -= f.z; s[c].w -= f.w;
            }
        }
    }

    warp_reduce_atomic(local, &g_acc[0]);
}

// ---------------------------------------------------------------------------
// Flow gradient: d-walk with register reuse (unchanged, runs on side stream).
__global__ void k_grad(const float* __restrict__ flow) {
    const float4* __restrict__ f4 = (const float4*)flow;
    const int t = threadIdx.x;
    const int qw = t % WQ;
    const int hs = t / WQ;                   // 0..3
    int blk = blockIdx.x;                    // over B*3 * (H/4) * GSEGD = 1152
    const int seg = blk % GSEGD; blk /= GSEGD;
    const int hq = blk % (H / 4);
    const int bc = blk / (H / 4);            // 0..5 (b*3 + c)
    const int h  = hq * 4 + hs;
    const int d0 = seg * GDSEG;

    const bool hasH = (h < H - 1);
    const bool hasW = (qw < WQ - 1);

    size_t base = (size_t)bc * DHWQ + (size_t)d0 * HWQ + (size_t)h * WQ + qw;
    float sdx = 0.f, sdy = 0.f, sdz = 0.f;
    float4 v = f4[base];

    const int dend = d0 + GDSEG;
#pragma unroll 4
    for (int d = d0; d < dend; d++) {
        sdz += fabsf(v.y - v.x) + fabsf(v.z - v.y) + fabsf(v.w - v.z);
        if (hasW) sdz += fabsf(flow[4 * base + 4] - v.w);
        if (hasH) {
            const float4 hn = f4[base + WQ];
            sdx += fabsf(hn.x - v.x) + fabsf(hn.y - v.y)
                 + fabsf(hn.z - v.z) + fabsf(hn.w - v.w);
        }
        if (d < D - 1) {
            const float4 dn = f4[base + HWQ];
            sdy += fabsf(dn.x - v.x) + fabsf(dn.y - v.y)
                 + fabsf(dn.z - v.z) + fabsf(dn.w - v.w);
            v = dn;
        }
        base += HWQ;
    }

    warp_reduce_atomic(sdx, &g_acc[1]);
    warp_reduce_atomic(sdy, &g_acc[2]);
    warp_reduce_atomic(sdz, &g_acc[3]);
}

// ---------------------------------------------------------------------------
__global__ void k_finalize(float* __restrict__ out) {
    const double L_sim = -(g_acc[0] / (double)NVOX);
    const double ndx = (double)B * 3.0 * D * (H - 1) * W;
    const double ndy = (double)B * 3.0 * (D - 1) * H * W;
    const double ndz = (double)B * 3.0 * D * H * (W - 1);
    const double L_reg = g_acc[1] / ndx + g_acc[2] / ndy + g_acc[3] / ndz;
    out[0] = (float)(L_sim + L_reg);
    out[1] = (float)L_sim;
    out[2] = (float)L_reg;
}

// ---------------------------------------------------------------------------
extern "C" void kernel_launch(void* const* d_in, const int* in_sizes, int n_in,
                              void* d_out, int out_size) {
    const float* I_fixed = (const float*)d_in[0];
    const float* I_moved = (const float*)d_in[1];
    const float* flow    = (const float*)d_in[2];
    float* out = (float*)d_out;

    static cudaStream_t s_side = 0;
    static cudaEvent_t ev_fork = 0, ev_join = 0;
    if (s_side == 0) {
        cudaStreamCreateWithFlags(&s_side, cudaStreamNonBlocking);
        cudaEventCreateWithFlags(&ev_fork, cudaEventDisableTiming);
        cudaEventCreateWithFlags(&ev_join, cudaEventDisableTiming);
    }

    k_zero<<<1, 32>>>();

    // Fork: k_grad (reads flow only) runs concurrently with pass12/pass3.
    cudaEventRecord(ev_fork, 0);
    cudaStreamWaitEvent(s_side, ev_fork, 0);
    k_grad<<<B * 3 * (H / 4) * GSEGD, 160, 0, s_side>>>(flow);
    cudaEventRecord(ev_join, s_side);

    k_pass12<<<B * D * NSEGH, W>>>(I_fixed, I_moved);
    k_pass3_cc<<<B * (H / 4) * SEG3, 160>>>();

    cudaStreamWaitEvent(0, ev_join, 0);
    k_finalize<<<1, 1>>>(out);
}

// round 11
// speedup vs baseline: 1.2931x; 1.0941x over previous
#include <cuda_runtime.h>
#include <cuda_fp16.h>

// Problem constants
#define B   2
#define D   160
#define H   192
#define W   160
#define HW  (H * W)          // 30720
#define DHW (D * H * W)      // 4915200
#define NVOX (B * DHW)       // 9830400 per channel
#define CH  5
#define WIN 9
#define PAD 4
#define INV_N (1.0f / 729.0f)

// 4-half units (pass3)
#define W4    (W / 4)        // 40
#define HW4   (HW / 4)       // 7680
#define DHW4  (DHW / 4)      // 1228800
#define NVOX4 (NVOX / 4)     // 2457600

// float4 units (grad)
#define WQ   (W / 4)         // 40
#define HWQ  (HW / 4)        // 7680
#define DHWQ (DHW / 4)       // 1228800

// H segmentation for k_pass12
#define HSEG  64
#define NSEGH (H / HSEG)     // 3
#define NCHUNK 18            // (HSEG + 2*PAD) / 4 rows staged per chunk

// D segmentation for k_pass3
#define SEG3  8
#define DSEG3 (D / SEG3)     // 20

// D segmentation for k_grad
#define GSEGD 4
#define GDSEG (D / GSEGD)    // 40

// Scratch — fp16 box-sums, uint2-typed for 8B alignment
__device__ uint2 g_bufH4[CH * NVOX4];
__device__ double g_acc[4];           // cc_sum, dx_sum, dy_sum, dz_sum

__device__ __forceinline__ void warp_reduce_atomic(float v, double* dst) {
#pragma unroll
    for (int off = 16; off > 0; off >>= 1)
        v += __shfl_down_sync(0xFFFFFFFFu, v, off);
    if ((threadIdx.x & 31) == 0) atomicAdd(dst, (double)v);
}

__device__ __forceinline__ float4 h4_to_f4(uint2 u) {
    const __half2 a = *reinterpret_cast<const __half2*>(&u.x);
    const __half2 b = *reinterpret_cast<const __half2*>(&u.y);
    const float2 fa = __half22float2(a);
    const float2 fb = __half22float2(b);
    return make_float4(fa.x, fa.y, fb.x, fb.y);
}

__global__ void k_zero() {
    if (threadIdx.x < 4) g_acc[threadIdx.x] = 0.0;
}

// ---------------------------------------------------------------------------
// Fused pass 1+2, software-pipelined: LDG(chunk j+1) overlaps PROC(chunk j).
// Rows h0-4 .. h0+67 processed in 18 chunks of 4; emits h0 .. h0+63.
__global__ void k_pass12(const float* __restrict__ F, const float* __restrict__ M) {
    __shared__ float stg[2][4][2][W + 2 * PAD];  // [buf][row][f/m][w] 10.75KB
    __shared__ float ring[WIN][CH][W];           // 28.8KB

    __half2* __restrict__ bufH2 = (__half2*)g_bufH4;

    const int w = threadIdx.x;
    int blk = blockIdx.x;                        // over B*D*NSEGH = 960
    const int hs = blk % NSEGH; blk /= NSEGH;
    const int d  = blk % D;
    const int b  = blk / D;
    const int h0 = hs * HSEG;

    const size_t plane = (size_t)(b * D + d) * HW;
    const float* __restrict__ Fp = F + plane;
    const float* __restrict__ Mp = M + plane;
    const bool even = ((w & 1) == 0);

    // Zero ring column (thread-private) and staging halos (once).
#pragma unroll
    for (int sl = 0; sl < WIN; sl++)
#pragma unroll
        for (int c = 0; c < CH; c++) ring[sl][c][w] = 0.f;
    if (w < PAD) {
#pragma unroll
        for (int bu = 0; bu < 2; bu++)
#pragma unroll
            for (int r = 0; r < 4; r++)
#pragma unroll
                for (int c = 0; c < 2; c++) {
                    stg[bu][r][c][w] = 0.f;
                    stg[bu][r][c][w + W + PAD] = 0.f;
                }
    }

    float rf[4], rm[4];

#define LDGCHUNK(jj)                                                         \
    {                                                                        \
        _Pragma("unroll")                                                    \
        for (int i = 0; i < 4; i++) {                                        \
            const int r_ = h0 - 4 + 4 * (jj) + i;                            \
            const bool v_ = (r_ >= 0 && r_ < H);                             \
            rf[i] = v_ ? Fp[r_ * W + w] : 0.f;                               \
            rm[i] = v_ ? Mp[r_ * W + w] : 0.f;                               \
        }                                                                    \
    }

#define STSCHUNK(bu)                                                         \
    {                                                                        \
        _Pragma("unroll")                                                    \
        for (int i = 0; i < 4; i++) {                                        \
            stg[bu][i][0][w + PAD] = rf[i];                                  \
            stg[bu][i][1][w + PAD] = rm[i];                                  \
        }                                                                    \
    }

    float s0 = 0.f, s1 = 0.f, s2 = 0.f, s3 = 0.f, s4 = 0.f;
    int slot = 0;

    // PROC staged row i of buffer bu: 9-tap W box, update ring + running sums.
#define PROC(bu, i)                                                          \
    {                                                                        \
        float n0 = 0.f, n1 = 0.f, n2 = 0.f, n3 = 0.f, n4 = 0.f;              \
        _Pragma("unroll")                                                    \
        for (int k = 0; k < WIN; k++) {                                      \
            const float fk = stg[bu][i][0][w + k];                           \
            const float mk = stg[bu][i][1][w + k];                           \
            n0 += fk; n1 += mk;                                              \
            n2 = fmaf(fk, fk, n2);                                           \
            n3 = fmaf(mk, mk, n3);                                           \
            n4 = fmaf(fk, mk, n4);                                           \
        }                                                                    \
        s0 += n0 - ring[slot][0][w]; ring[slot][0][w] = n0;                  \
        s1 += n1 - ring[slot][1][w]; ring[slot][1][w] = n1;                  \
        s2 += n2 - ring[slot][2][w]; ring[slot][2][w] = n2;                  \
        s3 += n3 - ring[slot][3][w]; ring[slot][3][w] = n3;                  \
        s4 += n4 - ring[slot][4][w]; ring[slot][4][w] = n4;                  \
        slot = (slot == WIN - 1) ? 0 : slot + 1;                             \
    }

    // Even lanes store packed {own, lane+1} half2 per channel.
#define EMIT(h_)                                                             \
    {                                                                        \
        const float t0 = __shfl_down_sync(0xFFFFFFFFu, s0, 1);               \
        const float t1 = __shfl_down_sync(0xFFFFFFFFu, s1, 1);               \
        const float t2 = __shfl_down_sync(0xFFFFFFFFu, s2, 1);               \
        const float t3 = __shfl_down_sync(0xFFFFFFFFu, s3, 1);               \
        const float t4 = __shfl_down_sync(0xFFFFFFFFu, s4, 1);               \
        if (even) {                                                          \
            const size_t o2 = (plane + (size_t)(h_) * W + w) >> 1;           \
            bufH2[((size_t)0 * NVOX >> 1) + o2] = __floats2half2_rn(s0, t0); \
            bufH2[((size_t)1 * NVOX >> 1) + o2] = __floats2half2_rn(s1, t1); \
            bufH2[((size_t)2 * NVOX >> 1) + o2] = __floats2half2_rn(s2, t2); \
            bufH2[((size_t)3 * NVOX >> 1) + o2] = __floats2half2_rn(s3, t3); \
            bufH2[((size_t)4 * NVOX >> 1) + o2] = __floats2half2_rn(s4, t4); \
        }                                                                    \
    }

    // Prologue: stage chunk 0.
    LDGCHUNK(0);
    STSCHUNK(0);
    __syncthreads();

#pragma unroll 1
    for (int j = 0; j < NCHUNK; j++) {
        // Prefetch next chunk into registers (overlaps with PROC below).
        if (j < NCHUNK - 1) LDGCHUNK(j + 1);

        const int bu = j & 1;
        if (j >= 2) {
            const int hb = h0 + 4 * (j - 2);   // first emit h of this chunk
            PROC(bu, 0) EMIT(hb + 0);
            PROC(bu, 1) EMIT(hb + 1);
            PROC(bu, 2) EMIT(hb + 2);
            PROC(bu, 3) EMIT(hb + 3);
        } else {
            PROC(bu, 0) PROC(bu, 1) PROC(bu, 2) PROC(bu, 3)
        }

        if (j < NCHUNK - 1) {
            STSCHUNK(bu ^ 1);
            __syncthreads();
        }
    }
#undef LDGCHUNK
#undef STSCHUNK
#undef PROC
#undef EMIT
}

// ---------------------------------------------------------------------------
// Pass 3: two-pointer D running window (unchanged from R10 best).
__global__ void __launch_bounds__(160) k_pass3_cc() {
    const int t = threadIdx.x;
    const int qw = t % W4;
    const int hs = t / W4;                   // 0..3
    int blk = blockIdx.x;                    // over B * (H/4) * SEG3 = 768
    const int seg = blk % SEG3; blk /= SEG3;
    const int hq = blk % (H / 4);
    const int b  = blk / (H / 4);
    const int h  = hq * 4 + hs;
    const int d0 = seg * DSEG3;

    const size_t col = (size_t)b * DHW4 + (size_t)h * W4 + qw;

    float4 s[CH];
#pragma unroll
    for (int c = 0; c < CH; c++) s[c] = make_float4(0.f, 0.f, 0.f, 0.f);

#pragma unroll 1
    for (int i = 0; i < WIN; i++) {
        const int d = d0 - PAD + i;
        if (d >= 0) {
#pragma unroll
            for (int c = 0; c < CH; c++) {
                const float4 f = h4_to_f4(g_bufH4[(size_t)c * NVOX4 + col + (size_t)d * HW4]);
                s[c].x += f.x; s[c].y += f.y; s[c].z += f.z; s[c].w += f.w;
            }
        }
    }

    float local = 0.f;
#pragma unroll 2
    for (int u = 0; u < DSEG3; u++) {
        const int d = d0 + u;
#define CCC(comp)                                                            \
        {                                                                    \
            const float mf  = s[0].comp * INV_N;                             \
            const float mm  = s[1].comp * INV_N;                             \
            const float vF  = s[2].comp - mf * mf;                           \
            const float vM  = s[3].comp - mm * mm;                           \
            const float cov = s[4].comp - mf * mm;                           \
            local += (cov * cov) / (vF * vM + 1e-8f);                        \
        }
        CCC(x) CCC(y) CCC(z) CCC(w)
#undef CCC

        const int dn = d + PAD + 1;
        const int dm = d - PAD;
        if (dn < D) {
#pragma unroll
            for (int c = 0; c < CH; c++) {
                const float4 f = h4_to_f4(g_bufH4[(size_t)c * NVOX4 + col + (size_t)dn * HW4]);
                s[c].x += f.x; s[c].y += f.y; s[c].z += f.z; s[c].w += f.w;
            }
        }
        if (dm >= 0) {
#pragma unroll
            for (int c = 0; c < CH; c++) {
                const float4 f = h4_to_f4(g_bufH4[(size_t)c * NVOX4 + col + (size_t)dm * HW4]);
                s[c].x -= f.x; s[c].y -= f.y; s[c].z -= f.z; s[c].w -= f.w;
            }
        }
    }

    warp_reduce_atomic(local, &g_acc[0]);
}

// ---------------------------------------------------------------------------
// Flow gradient: d-walk with register reuse (unchanged, runs on side stream).
__global__ void k_grad(const float* __restrict__ flow) {
    const float4* __restrict__ f4 = (const float4*)flow;
    const int t = threadIdx.x;
    const int qw = t % WQ;
    const int hs = t / WQ;                   // 0..3
    int blk = blockIdx.x;                    // over B*3 * (H/4) * GSEGD = 1152
    const int seg = blk % GSEGD; blk /= GSEGD;
    const int hq = blk % (H / 4);
    const int bc = blk / (H / 4);            // 0..5 (b*3 + c)
    const int h  = hq * 4 + hs;
    const int d0 = seg * GDSEG;

    const bool hasH = (h < H - 1);
    const bool hasW = (qw < WQ - 1);

    size_t base = (size_t)bc * DHWQ + (size_t)d0 * HWQ + (size_t)h * WQ + qw;
    float sdx = 0.f, sdy = 0.f, sdz = 0.f;
    float4 v = f4[base];

    const int dend = d0 + GDSEG;
#pragma unroll 4
    for (int d = d0; d < dend; d++) {
        sdz += fabsf(v.y - v.x) + fabsf(v.z - v.y) + fabsf(v.w - v.z);
        if (hasW) sdz += fabsf(flow[4 * base + 4] - v.w);
        if (hasH) {
            const float4 hn = f4[base + WQ];
            sdx += fabsf(hn.x - v.x) + fabsf(hn.y - v.y)
                 + fabsf(hn.z - v.z) + fabsf(hn.w - v.w);
        }
        if (d < D - 1) {
            const float4 dn = f4[base + HWQ];
            sdy += fabsf(dn.x - v.x) + fabsf(dn.y - v.y)
                 + fabsf(dn.z - v.z) + fabsf(dn.w - v.w);
            v = dn;
        }
        base += HWQ;
    }

    warp_reduce_atomic(sdx, &g_acc[1]);
    warp_reduce_atomic(sdy, &g_acc[2]);
    warp_reduce_atomic(sdz, &g_acc[3]);
}

// ---------------------------------------------------------------------------
__global__ void k_finalize(float* __restrict__ out) {
    const double L_sim = -(g_acc[0] / (double)NVOX);
    const double ndx = (double)B * 3.0 * D * (H - 1) * W;
    const double ndy = (double)B * 3.0 * (D - 1) * H * W;
    const double ndz = (double)B * 3.0 * D * H * (W - 1);
    const double L_reg = g_acc[1] / ndx + g_acc[2] / ndy + g_acc[3] / ndz;
    out[0] = (float)(L_sim + L_reg);
    out[1] = (float)L_sim;
    out[2] = (float)L_reg;
}

// ---------------------------------------------------------------------------
extern "C" void kernel_launch(void* const* d_in, const int* in_sizes, int n_in,
                              void* d_out, int out_size) {
    const float* I_fixed = (const float*)d_in[0];
    const float* I_moved = (const float*)d_in[1];
    const float* flow    = (const float*)d_in[2];
    float* out = (float*)d_out;

    static cudaStream_t s_side = 0;
    static cudaEvent_t ev_fork = 0, ev_join = 0;
    if (s_side == 0) {
        cudaStreamCreateWithFlags(&s_side, cudaStreamNonBlocking);
        cudaEventCreateWithFlags(&ev_fork, cudaEventDisableTiming);
        cudaEventCreateWithFlags(&ev_join, cudaEventDisableTiming);
    }

    k_zero<<<1, 32>>>();

    // Fork: k_grad (reads flow only) runs concurrently with pass12/pass3.
    cudaEventRecord(ev_fork, 0);
    cudaStreamWaitEvent(s_side, ev_fork, 0);
    k_grad<<<B * 3 * (H / 4) * GSEGD, 160, 0, s_side>>>(flow);
    cudaEventRecord(ev_join, s_side);

    k_pass12<<<B * D * NSEGH, W>>>(I_fixed, I_moved);
    k_pass3_cc<<<B * (H / 4) * SEG3, 160>>>();

    cudaStreamWaitEvent(0, ev_join, 0);
    k_finalize<<<1, 1>>>(out);
}

// round 12
// speedup vs baseline: 1.3047x; 1.0090x over previous
#include <cuda_runtime.h>
#include <cuda_fp16.h>

// Problem constants
#define B   2
#define D   160
#define H   192
#define W   160
#define HW  (H * W)          // 30720
#define DHW (D * H * W)      // 4915200
#define NVOX (B * DHW)       // 9830400 per channel
#define CH  5
#define WIN 9
#define PAD 4
#define INV_N (1.0f / 729.0f)

// 4-half units (pass3)
#define W4    (W / 4)        // 40
#define HW4   (HW / 4)       // 7680
#define DHW4  (DHW / 4)      // 1228800
#define NVOX4 (NVOX / 4)     // 2457600

// float4 units (grad)
#define WQ   (W / 4)         // 40
#define HWQ  (HW / 4)        // 7680
#define DHWQ (DHW / 4)       // 1228800

// H segmentation for k_pass12
#define HSEG  64
#define NSEGH (H / HSEG)     // 3
#define NCHUNK 18            // (HSEG + 2*PAD) / 4 rows per chunk

// D segmentation for k_pass3
#define SEG3  8
#define DSEG3 (D / SEG3)     // 20

// D segmentation for k_grad
#define GSEGD 4
#define GDSEG (D / GSEGD)    // 40

// Scratch — fp16 box-sums, uint2-typed for 8B alignment
__device__ uint2 g_bufH4[CH * NVOX4];
__device__ double g_acc[4];           // cc_sum, dx_sum, dy_sum, dz_sum

typedef unsigned long long ull;

// ---- packed f32x2 helpers (Blackwell PTX) ----------------------------------
__device__ __forceinline__ ull pk2(float x, float y) {
    ull r; asm("mov.b64 %0, {%1, %2};" : "=l"(r) : "f"(x), "f"(y)); return r;
}
__device__ __forceinline__ void upk2(ull a, float& x, float& y) {
    asm("mov.b64 {%0, %1}, %2;" : "=f"(x), "=f"(y) : "l"(a));
}
__device__ __forceinline__ ull add2(ull a, ull b) {
    ull d; asm("add.rn.f32x2 %0, %1, %2;" : "=l"(d) : "l"(a), "l"(b)); return d;
}
__device__ __forceinline__ ull fma2(ull a, ull b, ull c) {
    ull d; asm("fma.rn.f32x2 %0, %1, %2, %3;" : "=l"(d) : "l"(a), "l"(b), "l"(c)); return d;
}

__device__ __forceinline__ void warp_reduce_atomic(float v, double* dst) {
#pragma unroll
    for (int off = 16; off > 0; off >>= 1)
        v += __shfl_down_sync(0xFFFFFFFFu, v, off);
    if ((threadIdx.x & 31) == 0) atomicAdd(dst, (double)v);
}

__device__ __forceinline__ float4 h4_to_f4(uint2 u) {
    const __half2 a = *reinterpret_cast<const __half2*>(&u.x);
    const __half2 b = *reinterpret_cast<const __half2*>(&u.y);
    const float2 fa = __half22float2(a);
    const float2 fb = __half22float2(b);
    return make_float4(fa.x, fa.y, fb.x, fb.y);
}

__global__ void k_zero() {
    if (threadIdx.x < 4) g_acc[threadIdx.x] = 0.0;
}

// ---------------------------------------------------------------------------
// Fused pass 1+2, software-pipelined + packed f32x2 taps.
// Staging holds (f,m) interleaved float2 -> 9 LDS.64 taps per row.
// ch0/1 and ch2/3 computed packed; ring packed likewise.
__global__ void k_pass12(const float* __restrict__ F, const float* __restrict__ M) {
    __shared__ float2 stg[2][4][W + 2 * PAD];    // (f,m) pairs, 10.75KB
    __shared__ float2 ring01[WIN][W];            // (sumF, sumM)   11.5KB
    __shared__ float2 ring23[WIN][W];            // (sumF2, sumM2) 11.5KB
    __shared__ float  ring4 [WIN][W];            // sumFM          5.76KB

    __half2* __restrict__ bufH2 = (__half2*)g_bufH4;

    const int w = threadIdx.x;
    int blk = blockIdx.x;                        // over B*D*NSEGH = 960
    const int hs = blk % NSEGH; blk /= NSEGH;
    const int d  = blk % D;
    const int b  = blk / D;
    const int h0 = hs * HSEG;

    const size_t plane = (size_t)(b * D + d) * HW;
    const float* __restrict__ Fp = F + plane;
    const float* __restrict__ Mp = M + plane;
    const bool even = ((w & 1) == 0);
    const ull NEG1 = pk2(-1.f, -1.f);

    // Zero ring column (thread-private) and staging halos (once).
#pragma unroll
    for (int sl = 0; sl < WIN; sl++) {
        ring01[sl][w] = make_float2(0.f, 0.f);
        ring23[sl][w] = make_float2(0.f, 0.f);
        ring4 [sl][w] = 0.f;
    }
    if (w < PAD) {
#pragma unroll
        for (int bu = 0; bu < 2; bu++)
#pragma unroll
            for (int r = 0; r < 4; r++) {
                stg[bu][r][w] = make_float2(0.f, 0.f);
                stg[bu][r][w + W + PAD] = make_float2(0.f, 0.f);
            }
    }

    float rf[4], rm[4];

#define LDGCHUNK(jj)                                                         \
    {                                                                        \
        _Pragma("unroll")                                                    \
        for (int i = 0; i < 4; i++) {                                        \
            const int r_ = h0 - 4 + 4 * (jj) + i;                            \
            const bool v_ = (r_ >= 0 && r_ < H);                             \
            rf[i] = v_ ? Fp[r_ * W + w] : 0.f;                               \
            rm[i] = v_ ? Mp[r_ * W + w] : 0.f;                               \
        }                                                                    \
    }

#define STSCHUNK(bu)                                                         \
    {                                                                        \
        _Pragma("unroll")                                                    \
        for (int i = 0; i < 4; i++)                                          \
            stg[bu][i][w + PAD] = make_float2(rf[i], rm[i]);                 \
    }

    // Running H-window sums: packed (s0,s1), (s2,s3), scalar s4.
    ull s01 = 0ull, s23 = 0ull;
    float s4 = 0.f;
    int slot = 0;

    // PROC staged row i of buffer bu: packed 9-tap W box + ring update.
#define PROC(bu, i)                                                          \
    {                                                                        \
        ull a01 = 0ull, a23 = 0ull;                                          \
        float a4 = 0.f;                                                      \
        _Pragma("unroll")                                                    \
        for (int k = 0; k < WIN; k++) {                                      \
            const float2 P = stg[bu][i][w + k];                              \
            const ull Pp = pk2(P.x, P.y);                                    \
            a01 = add2(a01, Pp);                                             \
            a23 = fma2(Pp, Pp, a23);                                         \
            a4  = fmaf(P.x, P.y, a4);                                        \
        }                                                                    \
        const float2 r01 = ring01[slot][w];                                  \
        const float2 r23 = ring23[slot][w];                                  \
        const float  r4  = ring4 [slot][w];                                  \
        s01 = add2(fma2(pk2(r01.x, r01.y), NEG1, s01), a01);                 \
        s23 = add2(fma2(pk2(r23.x, r23.y), NEG1, s23), a23);                 \
        s4 += a4 - r4;                                                       \
        float a0_, a1_, a2_, a3_;                                            \
        upk2(a01, a0_, a1_); upk2(a23, a2_, a3_);                            \
        ring01[slot][w] = make_float2(a0_, a1_);                             \
        ring23[slot][w] = make_float2(a2_, a3_);                             \
        ring4 [slot][w] = a4;                                                \
        slot = (slot == WIN - 1) ? 0 : slot + 1;                             \
    }

    // Even lanes store packed {own, lane+1} half2 per channel.
#define EMIT(h_)                                                             \
    {                                                                        \
        float s0_, s1_, s2_, s3_;                                            \
        upk2(s01, s0_, s1_); upk2(s23, s2_, s3_);                            \
        const float t0 = __shfl_down_sync(0xFFFFFFFFu, s0_, 1);              \
        const float t1 = __shfl_down_sync(0xFFFFFFFFu, s1_, 1);              \
        const float t2 = __shfl_down_sync(0xFFFFFFFFu, s2_, 1);              \
        const float t3 = __shfl_down_sync(0xFFFFFFFFu, s3_, 1);              \
        const float t4 = __shfl_down_sync(0xFFFFFFFFu, s4, 1);               \
        if (even) {                                                          \
            const size_t o2 = (plane + (size_t)(h_) * W + w) >> 1;           \
            bufH2[((size_t)0 * NVOX >> 1) + o2] = __floats2half2_rn(s0_, t0);\
            bufH2[((size_t)1 * NVOX >> 1) + o2] = __floats2half2_rn(s1_, t1);\
            bufH2[((size_t)2 * NVOX >> 1) + o2] = __floats2half2_rn(s2_, t2);\
            bufH2[((size_t)3 * NVOX >> 1) + o2] = __floats2half2_rn(s3_, t3);\
            bufH2[((size_t)4 * NVOX >> 1) + o2] = __floats2half2_rn(s4, t4); \
        }                                                                    \
    }

    // Prologue: stage chunk 0.
    LDGCHUNK(0);
    STSCHUNK(0);
    __syncthreads();

#pragma unroll 1
    for (int j = 0; j < NCHUNK; j++) {
        if (j < NCHUNK - 1) LDGCHUNK(j + 1);   // prefetch overlaps PROC

        const int bu = j & 1;
        if (j >= 2) {
            const int hb = h0 + 4 * (j - 2);
            PROC(bu, 0) EMIT(hb + 0);
            PROC(bu, 1) EMIT(hb + 1);
            PROC(bu, 2) EMIT(hb + 2);
            PROC(bu, 3) EMIT(hb + 3);
        } else {
            PROC(bu, 0) PROC(bu, 1) PROC(bu, 2) PROC(bu, 3)
        }

        if (j < NCHUNK - 1) {
            STSCHUNK(bu ^ 1);
            __syncthreads();
        }
    }
#undef LDGCHUNK
#undef STSCHUNK
#undef PROC
#undef EMIT
}

// ---------------------------------------------------------------------------
// Pass 3: two-pointer D running window (unchanged from R11 best).
__global__ void __launch_bounds__(160) k_pass3_cc() {
    const int t = threadIdx.x;
    const int qw = t % W4;
    const int hs = t / W4;                   // 0..3
    int blk = blockIdx.x;                    // over B * (H/4) * SEG3 = 768
    const int seg = blk % SEG3; blk /= SEG3;
    const int hq = blk % (H / 4);
    const int b  = blk / (H / 4);
    const int h  = hq * 4 + hs;
    const int d0 = seg * DSEG3;

    const size_t col = (size_t)b * DHW4 + (size_t)h * W4 + qw;

    float4 s[CH];
#pragma unroll
    for (int c = 0; c < CH; c++) s[c] = make_float4(0.f, 0.f, 0.f, 0.f);

#pragma unroll 1
    for (int i = 0; i < WIN; i++) {
        const int d = d0 - PAD + i;
        if (d >= 0) {
#pragma unroll
            for (int c = 0; c < CH; c++) {
                const float4 f = h4_to_f4(g_bufH4[(size_t)c * NVOX4 + col + (size_t)d * HW4]);
                s[c].x += f.x; s[c].y += f.y; s[c].z += f.z; s[c].w += f.w;
            }
        }
    }

    float local = 0.f;
#pragma unroll 2
    for (int u = 0; u < DSEG3; u++) {
        const int d = d0 + u;
#define CCC(comp)                                                            \
        {                                                                    \
            const float mf  = s[0].comp * INV_N;                             \
            const float mm  = s[1].comp * INV_N;                             \
            const float vF  = s[2].comp - mf * mf;                           \
            const float vM  = s[3].comp - mm * mm;                           \
            const float cov = s[4].comp - mf * mm;                           \
            local += (cov * cov) / (vF * vM + 1e-8f);                        \
        }
        CCC(x) CCC(y) CCC(z) CCC(w)
#undef CCC

        const int dn = d + PAD + 1;
        const int dm = d - PAD;
        if (dn < D) {
#pragma unroll
            for (int c = 0; c < CH; c++) {
                const float4 f = h4_to_f4(g_bufH4[(size_t)c * NVOX4 + col + (size_t)dn * HW4]);
                s[c].x += f.x; s[c].y += f.y; s[c].z += f.z; s[c].w += f.w;
            }
        }
        if (dm >= 0) {
#pragma unroll
            for (int c = 0; c < CH; c++) {
                const float4 f = h4_to_f4(g_bufH4[(size_t)c * NVOX4 + col + (size_t)dm * HW4]);
                s[c].x -= f.x; s[c].y -= f.y; s[c].z -= f.z; s[c].w -= f.w;
            }
        }
    }

    warp_reduce_atomic(local, &g_acc[0]);
}

// ---------------------------------------------------------------------------
// Flow gradient: d-walk with register reuse (unchanged, side stream).
__global__ void k_grad(const float* __restrict__ flow) {
    const float4* __restrict__ f4 = (const float4*)flow;
    const int t = threadIdx.x;
    const int qw = t % WQ;
    const int hs = t / WQ;                   // 0..3
    int blk = blockIdx.x;                    // over B*3 * (H/4) * GSEGD = 1152
    const int seg = blk % GSEGD; blk /= GSEGD;
    const int hq = blk % (H / 4);
    const int bc = blk / (H / 4);            // 0..5 (b*3 + c)
    const int h  = hq * 4 + hs;
    const int d0 = seg * GDSEG;

    const bool hasH = (h < H - 1);
    const bool hasW = (qw < WQ - 1);

    size_t base = (size_t)bc * DHWQ + (size_t)d0 * HWQ + (size_t)h * WQ + qw;
    float sdx = 0.f, sdy = 0.f, sdz = 0.f;
    float4 v = f4[base];

    const int dend = d0 + GDSEG;
#pragma unroll 4
    for (int d = d0; d < dend; d++) {
        sdz += fabsf(v.y - v.x) + fabsf(v.z - v.y) + fabsf(v.w - v.z);
        if (hasW) sdz += fabsf(flow[4 * base + 4] - v.w);
        if (hasH) {
            const float4 hn = f4[base + WQ];
            sdx += fabsf(hn.x - v.x) + fabsf(hn.y - v.y)
                 + fabsf(hn.z - v.z) + fabsf(hn.w - v.w);
        }
        if (d < D - 1) {
            const float4 dn = f4[base + HWQ];
            sdy += fabsf(dn.x - v.x) + fabsf(dn.y - v.y)
                 + fabsf(dn.z - v.z) + fabsf(dn.w - v.w);
            v = dn;
        }
        base += HWQ;
    }

    warp_reduce_atomic(sdx, &g_acc[1]);
    warp_reduce_atomic(sdy, &g_acc[2]);
    warp_reduce_atomic(sdz, &g_acc[3]);
}

// ---------------------------------------------------------------------------
__global__ void k_finalize(float* __restrict__ out) {
    const double L_sim = -(g_acc[0] / (double)NVOX);
    const double ndx = (double)B * 3.0 * D * (H - 1) * W;
    const double ndy = (double)B * 3.0 * (D - 1) * H * W;
    const double ndz = (double)B * 3.0 * D * H * (W - 1);
    const double L_reg = g_acc[1] / ndx + g_acc[2] / ndy + g_acc[3] / ndz;
    out[0] = (float)(L_sim + L_reg);
    out[1] = (float)L_sim;
    out[2] = (float)L_reg;
}

// ---------------------------------------------------------------------------
extern "C" void kernel_launch(void* const* d_in, const int* in_sizes, int n_in,
                              void* d_out, int out_size) {
    const float* I_fixed = (const float*)d_in[0];
    const float* I_moved = (const float*)d_in[1];
    const float* flow    = (const float*)d_in[2];
    float* out = (float*)d_out;

    static cudaStream_t s_side = 0;
    static cudaEvent_t ev_fork = 0, ev_join = 0;
    if (s_side == 0) {
        cudaStreamCreateWithFlags(&s_side, cudaStreamNonBlocking);
        cudaEventCreateWithFlags(&ev_fork, cudaEventDisableTiming);
        cudaEventCreateWithFlags(&ev_join, cudaEventDisableTiming);
    }

    k_zero<<<1, 32>>>();

    // Fork: k_grad (reads flow only) runs concurrently with pass12/pass3.
    cudaEventRecord(ev_fork, 0);
    cudaStreamWaitEvent(s_side, ev_fork, 0);
    k_grad<<<B * 3 * (H / 4) * GSEGD, 160, 0, s_side>>>(flow);
    cudaEventRecord(ev_join, s_side);

    k_pass12<<<B * D * NSEGH, W>>>(I_fixed, I_moved);
    k_pass3_cc<<<B * (H / 4) * SEG3, 160>>>();

    cudaStreamWaitEvent(0, ev_join, 0);
    k_finalize<<<1, 1>>>(out);
}